// round 12
// baseline (speedup 1.0000x reference)
#include <cuda_runtime.h>
#include <cuda_fp16.h>
#include <math.h>
#include <stdint.h>

// Problem constants
#define LL    1024
#define DD    1024
#define HH    16
#define DPT   64
#define BS    16
#define NTOK  16384

// Scratch (static device globals; no runtime allocation)
__device__ __half g_ah[NTOK * DD];   // activation hi (also ctx hi after attn)
__device__ __half g_al[NTOK * DD];   // activation lo (also ctx lo after attn)
__device__ __half g_wh[DD * DD];
__device__ __half g_wl[DD * DD];
__device__ __half g_qh[NTOK * DD];
__device__ __half g_ql[NTOK * DD];
__device__ __half g_kh[NTOK * DD];
__device__ __half g_kl[NTOK * DD];
__device__ __half g_vh[NTOK * DD];
__device__ __half g_vl[NTOK * DD];

// ===========================================================================
// helpers
// ===========================================================================
__device__ __forceinline__ uint32_t smem_to_u32(const void* smem_ptr) {
    uint32_t addr;
    asm("{ .reg .u64 tmp; cvta.to.shared.u64 tmp, %1; cvt.u32.u64 %0, tmp; }"
        : "=r"(addr) : "l"(smem_ptr));
    return addr;
}

#define CP_ASYNC16(dst_u32, src_ptr) \
    asm volatile("cp.async.cg.shared.global [%0], [%1], 16;" \
                 :: "r"(dst_u32), "l"(src_ptr) : "memory")
#define CP_COMMIT() \
    asm volatile("cp.async.commit_group;" ::: "memory")
#define CP_WAIT(N) \
    asm volatile("cp.async.wait_group %0;" :: "n"(N) : "memory")

#define LDSM4(r, addr) \
    asm volatile("ldmatrix.sync.aligned.m8n8.x4.shared.b16 {%0,%1,%2,%3}, [%4];" \
                 : "=r"((r)[0]), "=r"((r)[1]), "=r"((r)[2]), "=r"((r)[3]) \
                 : "r"(addr))
#define LDSM2(r, addr) \
    asm volatile("ldmatrix.sync.aligned.m8n8.x2.shared.b16 {%0,%1}, [%2];" \
                 : "=r"((r)[0]), "=r"((r)[1]) : "r"(addr))
#define LDSM2T(r, addr) \
    asm volatile("ldmatrix.sync.aligned.m8n8.x2.trans.shared.b16 {%0,%1}, [%2];" \
                 : "=r"((r)[0]), "=r"((r)[1]) : "r"(addr))

// f16 inputs, f32 accumulate (main term)
#define MMAF(d, a, b) \
    asm volatile("mma.sync.aligned.m16n8k16.row.col.f32.f16.f16.f32 " \
                 "{%0,%1,%2,%3}, {%4,%5,%6,%7}, {%8,%9}, {%0,%1,%2,%3};" \
                 : "+f"((d)[0]), "+f"((d)[1]), "+f"((d)[2]), "+f"((d)[3]) \
                 : "r"((a)[0]), "r"((a)[1]), "r"((a)[2]), "r"((a)[3]), \
                   "r"((b)[0]), "r"((b)[1]))

// f16 inputs, f16 accumulate (correction terms, 2x rate)
#define MMAH(d, a, b) \
    asm volatile("mma.sync.aligned.m16n8k16.row.col.f16.f16.f16.f16 " \
                 "{%0,%1}, {%2,%3,%4,%5}, {%6,%7}, {%0,%1};" \
                 : "+r"((d)[0]), "+r"((d)[1]) \
                 : "r"((a)[0]), "r"((a)[1]), "r"((a)[2]), "r"((a)[3]), \
                   "r"((b)[0]), "r"((b)[1]))

// ===========================================================================
// Conversion kernels: fp32 -> fp16 hi/lo split
// ===========================================================================
__global__ __launch_bounds__(256) void conv_split(
    const float* __restrict__ A,
    __half* __restrict__ H, __half* __restrict__ L)
{
    size_t i = ((size_t)blockIdx.x * 256 + threadIdx.x) * 4;
    float4 v = *(const float4*)(A + i);
    __half h0 = __float2half_rn(v.x);
    __half h1 = __float2half_rn(v.y);
    __half h2 = __float2half_rn(v.z);
    __half h3 = __float2half_rn(v.w);
    __half l0 = __float2half_rn(v.x - __half2float(h0));
    __half l1 = __float2half_rn(v.y - __half2float(h1));
    __half l2 = __float2half_rn(v.z - __half2float(h2));
    __half l3 = __float2half_rn(v.w - __half2float(h3));
    __half2 hh0 = __halves2half2(h0, h1);
    __half2 hh1 = __halves2half2(h2, h3);
    __half2 ll0 = __halves2half2(l0, l1);
    __half2 ll1 = __halves2half2(l2, l3);
    *(__half2*)(H + i)     = hh0;
    *(__half2*)(H + i + 2) = hh1;
    *(__half2*)(L + i)     = ll0;
    *(__half2*)(L + i + 2) = ll1;
}

__global__ __launch_bounds__(256) void conv_wt(
    const float* __restrict__ W,
    __half* __restrict__ Th, __half* __restrict__ Tl)
{
    __shared__ float t[32][33];
    const int n0 = blockIdx.x * 32, k0 = blockIdx.y * 32;
    const int tx = threadIdx.x & 31, ty = threadIdx.x >> 5;
    #pragma unroll
    for (int j = 0; j < 32; j += 8)
        t[ty + j][tx] = W[(size_t)(k0 + ty + j) * 1024 + n0 + tx];
    __syncthreads();
    #pragma unroll
    for (int j = 0; j < 32; j += 8) {
        float v = t[tx][ty + j];
        __half h = __float2half_rn(v);
        __half l = __float2half_rn(v - __half2float(h));
        size_t o = (size_t)(n0 + ty + j) * 1024 + k0 + tx;
        Th[o] = h;
        Tl[o] = l;
    }
}

// ===========================================================================
// mma.sync GEMM (fp16x3, f16-accum corrections).
// mode 0: C = fp32 + bias. mode 1: (C+bias)*scale -> OH/OL fp16 hi/lo.
// ===========================================================================
#define STR    72
#define TILE_B (128 * STR * 2)
#define STAGE_B (4 * TILE_B)
#define GEMM_SMEM_BYTES (2 * STAGE_B)

__global__ __launch_bounds__(256, 1) void gemm_mma(
    const __half* __restrict__ Ah, const __half* __restrict__ Al,
    const __half* __restrict__ Bh, const __half* __restrict__ Bl,
    const float* __restrict__ bias, float* __restrict__ C,
    __half* __restrict__ OH, __half* __restrict__ OL,
    int mode, float scale)
{
    extern __shared__ char smc[];
    const uint32_t smb = smem_to_u32(smc);
    const int tid = threadIdx.x;
    const int lane = tid & 31, wid = tid >> 5;
    const int wm = wid & 1;
    const int wn = wid >> 1;
    const int m0 = blockIdx.y * 128, n0 = blockIdx.x * 128;

    const __half* srcs[4] = {
        Ah + (size_t)m0 * 1024, Al + (size_t)m0 * 1024,
        Bh + (size_t)n0 * 1024, Bl + (size_t)n0 * 1024 };

    const int rb = tid >> 3;
    const int g  = tid & 7;

    float acc[4][4][4];
    uint32_t cacc[4][4][2];
    #pragma unroll
    for (int mt = 0; mt < 4; mt++)
        #pragma unroll
        for (int nt = 0; nt < 4; nt++) {
            #pragma unroll
            for (int e = 0; e < 4; e++) acc[mt][nt][e] = 0.f;
            cacc[mt][nt][0] = 0u; cacc[mt][nt][1] = 0u;
        }

    auto load_stage = [&](int c, int buf) {
        const int kc = c * 64;
        #pragma unroll
        for (int t = 0; t < 4; t++) {
            const __half* sp = srcs[t];
            const uint32_t db = smb + buf * STAGE_B + t * TILE_B;
            #pragma unroll
            for (int it = 0; it < 4; it++) {
                const int row = rb + 32 * it;
                const uint32_t dst = db + (uint32_t)row * 144 + g * 16;
                const __half* src = sp + (size_t)row * 1024 + kc + g * 8;
                CP_ASYNC16(dst, src);
            }
        }
    };

    load_stage(0, 0);
    CP_COMMIT();

    for (int c = 0; c < 16; c++) {
        const int buf = c & 1;
        if (c < 15) {
            load_stage(c + 1, buf ^ 1);
            CP_COMMIT();
            CP_WAIT(1);
        } else {
            CP_WAIT(0);
        }
        __syncthreads();

        const uint32_t bA = smb + buf * STAGE_B;
        #pragma unroll
        for (int ks = 0; ks < 4; ks++) {
            uint32_t a_h[4][4], a_l[4][4], b_h[4][2], b_l[4][2];
            const uint32_t acol = (uint32_t)(ks * 16 + (lane >> 4) * 8) * 2;
            #pragma unroll
            for (int mt = 0; mt < 4; mt++) {
                const uint32_t off =
                    (uint32_t)((wm * 64 + mt * 16 + (lane & 15)) * STR) * 2 + acol;
                LDSM4(a_h[mt], bA + off);
                LDSM4(a_l[mt], bA + TILE_B + off);
            }
            const uint32_t bcol = (uint32_t)(ks * 16 + ((lane >> 3) & 1) * 8) * 2;
            #pragma unroll
            for (int nt = 0; nt < 4; nt++) {
                const uint32_t off =
                    (uint32_t)((wn * 32 + nt * 8 + (lane & 7)) * STR) * 2 + bcol;
                LDSM2(b_h[nt], bA + 2 * TILE_B + off);
                LDSM2(b_l[nt], bA + 3 * TILE_B + off);
            }
            #pragma unroll
            for (int mt = 0; mt < 4; mt++)
                #pragma unroll
                for (int nt = 0; nt < 4; nt++) {
                    MMAF(acc[mt][nt], a_h[mt], b_h[nt]);
                    MMAH(cacc[mt][nt], a_h[mt], b_l[nt]);
                    MMAH(cacc[mt][nt], a_l[mt], b_h[nt]);
                }
        }
        __syncthreads();
    }

    #pragma unroll
    for (int mt = 0; mt < 4; mt++) {
        const int row_lo = m0 + wm * 64 + mt * 16 + (lane >> 2);
        #pragma unroll
        for (int nt = 0; nt < 4; nt++) {
            const int col = n0 + wn * 32 + nt * 8 + (lane & 3) * 2;
            const float2 bb = __ldg((const float2*)(bias + col));
            float2 c01 = __half22float2(*(__half2*)&cacc[mt][nt][0]);
            float2 c23 = __half22float2(*(__half2*)&cacc[mt][nt][1]);
            float v0 = acc[mt][nt][0] + c01.x + bb.x;
            float v1 = acc[mt][nt][1] + c01.y + bb.y;
            float v2 = acc[mt][nt][2] + c23.x + bb.x;
            float v3 = acc[mt][nt][3] + c23.y + bb.y;
            if (mode == 0) {
                float2 o0; o0.x = v0; o0.y = v1;
                float2 o1; o1.x = v2; o1.y = v3;
                *(float2*)&C[(size_t)row_lo * 1024 + col]       = o0;
                *(float2*)&C[(size_t)(row_lo + 8) * 1024 + col] = o1;
            } else {
                v0 *= scale; v1 *= scale; v2 *= scale; v3 *= scale;
                __half h0 = __float2half_rn(v0);
                __half h1 = __float2half_rn(v1);
                __half h2 = __float2half_rn(v2);
                __half h3 = __float2half_rn(v3);
                __half2 hp0 = __halves2half2(h0, h1);
                __half2 hp1 = __halves2half2(h2, h3);
                __half2 lp0 = __halves2half2(
                    __float2half_rn(v0 - __half2float(h0)),
                    __float2half_rn(v1 - __half2float(h1)));
                __half2 lp1 = __halves2half2(
                    __float2half_rn(v2 - __half2float(h2)),
                    __float2half_rn(v3 - __half2float(h3)));
                *(__half2*)&OH[(size_t)row_lo * 1024 + col]       = hp0;
                *(__half2*)&OH[(size_t)(row_lo + 8) * 1024 + col] = hp1;
                *(__half2*)&OL[(size_t)row_lo * 1024 + col]       = lp0;
                *(__half2*)&OL[(size_t)(row_lo + 8) * 1024 + col] = lp1;
            }
        }
    }
}

// ===========================================================================
// Tensor-core attention (fp16x3). Block = (32 queries, bs), 512 threads.
// Writes ctx as fp16 hi/lo directly (feeds final projection).
// ===========================================================================
#define LSTR 1032
#define KSTR2 144
#define OFF_KV  132096
#define OFF_Q   205824
#define OFF_MB  215040
#define OFF_INV 219136
#define AT_SMEM 219264
#define KVBUF   36864
#define KVPART  18432

__global__ __launch_bounds__(512, 1) void attn_tc(
    const __half* __restrict__ Qh, const __half* __restrict__ Ql,
    const __half* __restrict__ Kh, const __half* __restrict__ Kl,
    const __half* __restrict__ Vh, const __half* __restrict__ Vl,
    const float* __restrict__ mask,
    __half* __restrict__ CtxH, __half* __restrict__ CtxL,
    float* __restrict__ amean)
{
    extern __shared__ char smc[];
    const uint32_t smb = smem_to_u32(smc);
    float*    s_log = (float*)smc;
    uint32_t* s_p   = (uint32_t*)smc;
    uint32_t* s_mb  = (uint32_t*)(smc + OFF_MB);
    float*    s_inv = (float*)(smc + OFF_INV);

    const int tid = threadIdx.x;
    const int lane = tid & 31, wid = tid >> 5;
    const int wm = wid & 1;
    const int wg = wid >> 1;
    const int bs = blockIdx.y;
    const int q0 = blockIdx.x * 32;
    const size_t tokbase = (size_t)bs * LL;

    {
        const float* mp = mask + (tokbase + q0) * LL;
        #pragma unroll 8
        for (int i = 0; i < 64; i++) {
            int linear = i * 512 + tid;
            float mv = mp[linear];
            unsigned b = __ballot_sync(0xFFFFFFFFu, mv != 0.0f);
            if (lane == 0) s_mb[linear >> 5] = b;
        }
    }

    float mean_acc[64];
    #pragma unroll
    for (int i = 0; i < 64; i++) mean_acc[i] = 0.f;

    auto load_kv = [&](const __half* Hsrc, const __half* Lsrc,
                       int kb, int buf, int h) {
        #pragma unroll
        for (int i = 0; i < 4; i++) {
            int gidx = tid + 512 * i;
            int part = gidx >> 10;
            int gg = gidx & 1023;
            int row = gg >> 3, d8 = gg & 7;
            const __half* src = (part ? Lsrc : Hsrc) +
                (tokbase + kb * 128 + row) * 1024 + h * 64 + d8 * 8;
            uint32_t dst = smb + OFF_KV + buf * KVBUF + part * KVPART
                         + row * KSTR2 + d8 * 16;
            CP_ASYNC16(dst, src);
        }
    };

    __syncthreads();

    for (int h = 0; h < HH; h++) {
        {
            int part = tid >> 8;
            int gg = tid & 255;
            int row = gg >> 3, d8 = gg & 7;
            const __half* src = (part ? Ql : Qh) +
                (tokbase + q0 + row) * 1024 + h * 64 + d8 * 8;
            uint4 val = *(const uint4*)src;
            *(uint4*)(smc + OFF_Q + part * 4608 + row * KSTR2 + d8 * 16) = val;
        }
        load_kv(Kh, Kl, 0, 0, h);
        CP_COMMIT();

        // ---- QK^T ----
        for (int kb = 0; kb < 8; kb++) {
            const int buf = kb & 1;
            if (kb < 7) {
                load_kv(Kh, Kl, kb + 1, buf ^ 1, h);
                CP_COMMIT();
                CP_WAIT(1);
            } else {
                CP_WAIT(0);
            }
            __syncthreads();

            const uint32_t kbh = smb + OFF_KV + buf * KVBUF;
            const uint32_t kbl = kbh + KVPART;
            float acc[2][4];
            uint32_t qc[2][2];
            #pragma unroll
            for (int nt = 0; nt < 2; nt++) {
                #pragma unroll
                for (int e = 0; e < 4; e++) acc[nt][e] = 0.f;
                qc[nt][0] = 0u; qc[nt][1] = 0u;
            }

            #pragma unroll
            for (int ks = 0; ks < 4; ks++) {
                uint32_t a_h[4], a_l[4];
                const uint32_t qoff =
                    (uint32_t)((wm * 16 + (lane & 15)) * STR
                               + ks * 16 + (lane >> 4) * 8) * 2;
                LDSM4(a_h, smb + OFF_Q + qoff);
                LDSM4(a_l, smb + OFF_Q + 4608 + qoff);
                #pragma unroll
                for (int nt = 0; nt < 2; nt++) {
                    uint32_t b_h[2], b_l[2];
                    const uint32_t koff =
                        (uint32_t)((wg * 16 + nt * 8 + (lane & 7)) * STR
                                   + ks * 16 + ((lane >> 3) & 1) * 8) * 2;
                    LDSM2(b_h, kbh + koff);
                    LDSM2(b_l, kbl + koff);
                    MMAF(acc[nt], a_h, b_h);
                    MMAH(qc[nt], a_h, b_l);
                    MMAH(qc[nt], a_l, b_h);
                }
            }
            const int r0 = wm * 16 + (lane >> 2);
            #pragma unroll
            for (int nt = 0; nt < 2; nt++) {
                const int c0 = kb * 128 + wg * 16 + nt * 8 + (lane & 3) * 2;
                const uint32_t w0 = s_mb[r0 * 32 + (c0 >> 5)];
                const uint32_t w1 = s_mb[(r0 + 8) * 32 + (c0 >> 5)];
                const int sh = c0 & 31;
                float2 c01 = __half22float2(*(__half2*)&qc[nt][0]);
                float2 c23 = __half22float2(*(__half2*)&qc[nt][1]);
                float2 o0, o1;
                o0.x = acc[nt][0] + c01.x + (((w0 >> sh) & 1) ? -1.0e9f : 0.f);
                o0.y = acc[nt][1] + c01.y + (((w0 >> (sh + 1)) & 1) ? -1.0e9f : 0.f);
                o1.x = acc[nt][2] + c23.x + (((w1 >> sh) & 1) ? -1.0e9f : 0.f);
                o1.y = acc[nt][3] + c23.y + (((w1 >> (sh + 1)) & 1) ? -1.0e9f : 0.f);
                *(float2*)&s_log[r0 * LSTR + c0]       = o0;
                *(float2*)&s_log[(r0 + 8) * LSTR + c0] = o1;
            }
            __syncthreads();
        }

        load_kv(Vh, Vl, 0, 0, h);
        CP_COMMIT();

        // ---- softmax; pack p as (f16 hi | f16 lo) in place ----
        #pragma unroll
        for (int rr = 0; rr < 2; rr++) {
            const int r = wid * 2 + rr;
            float mx = -3.4e38f;
            #pragma unroll 8
            for (int j = 0; j < 32; j++)
                mx = fmaxf(mx, s_log[r * LSTR + lane + 32 * j]);
            #pragma unroll
            for (int off = 16; off > 0; off >>= 1)
                mx = fmaxf(mx, __shfl_xor_sync(0xFFFFFFFFu, mx, off));
            float ssum = 0.f;
            #pragma unroll 8
            for (int j = 0; j < 32; j++) {
                const int idx = r * LSTR + lane + 32 * j;
                float p = __expf(s_log[idx] - mx);
                ssum += p;
                __half hh = __float2half_rn(p);
                float hf = __half2float(hh);
                __half lh = __float2half_rn(p - hf);
                s_p[idx] = (uint32_t)__half_as_ushort(hh)
                         | ((uint32_t)__half_as_ushort(lh) << 16);
            }
            #pragma unroll
            for (int off = 16; off > 0; off >>= 1)
                ssum += __shfl_xor_sync(0xFFFFFFFFu, ssum, off);
            if (lane == 0) s_inv[r] = 1.f / ssum;
        }
        __syncthreads();

        // ---- amean ----
        #pragma unroll 8
        for (int i = 0; i < 64; i++) {
            const int linear = i * 512 + tid;
            const int r = linear >> 10, c = linear & 1023;
            const uint32_t w = s_p[r * LSTR + c];
            float p = __half2float(__ushort_as_half((unsigned short)(w & 0xFFFFu)))
                    + __half2float(__ushort_as_half((unsigned short)(w >> 16)));
            mean_acc[i] += p * s_inv[r];
        }

        // ---- P @ V ----
        float cacc[4];
        uint32_t pc[2];
        #pragma unroll
        for (int e = 0; e < 4; e++) cacc[e] = 0.f;
        pc[0] = 0u; pc[1] = 0u;

        for (int kv = 0; kv < 8; kv++) {
            const int buf = kv & 1;
            if (kv < 7) {
                load_kv(Vh, Vl, kv + 1, buf ^ 1, h);
                CP_COMMIT();
                CP_WAIT(1);
            } else {
                CP_WAIT(0);
            }
            __syncthreads();

            const uint32_t vbh = smb + OFF_KV + buf * KVBUF;
            const uint32_t vbl = vbh + KVPART;
            const int r0 = wm * 16 + (lane >> 2);
            const int r1 = r0 + 8;

            #pragma unroll
            for (int ks = 0; ks < 8; ks++) {
                const int kk = kv * 128 + ks * 16 + (lane & 3) * 2;
                uint2 v00 = *(uint2*)&s_p[r0 * LSTR + kk];
                uint2 v02 = *(uint2*)&s_p[r0 * LSTR + kk + 8];
                uint2 v10 = *(uint2*)&s_p[r1 * LSTR + kk];
                uint2 v12 = *(uint2*)&s_p[r1 * LSTR + kk + 8];
                uint32_t a_h[4], a_l[4];
                a_h[0] = __byte_perm(v00.x, v00.y, 0x5410);
                a_l[0] = __byte_perm(v00.x, v00.y, 0x7632);
                a_h[1] = __byte_perm(v10.x, v10.y, 0x5410);
                a_l[1] = __byte_perm(v10.x, v10.y, 0x7632);
                a_h[2] = __byte_perm(v02.x, v02.y, 0x5410);
                a_l[2] = __byte_perm(v02.x, v02.y, 0x7632);
                a_h[3] = __byte_perm(v12.x, v12.y, 0x5410);
                a_l[3] = __byte_perm(v12.x, v12.y, 0x7632);

                uint32_t b_h[2], b_l[2];
                const uint32_t voff =
                    (uint32_t)((ks * 16 + (lane & 15)) * STR + wg * 8) * 2;
                LDSM2T(b_h, vbh + voff);
                LDSM2T(b_l, vbl + voff);

                MMAF(cacc, a_h, b_h);
                MMAH(pc, a_h, b_l);
                MMAH(pc, a_l, b_h);
            }
            __syncthreads();
        }

        // ---- write ctx as fp16 hi/lo (normalized) ----
        {
            const int r0 = wm * 16 + (lane >> 2);
            const float inv0 = s_inv[r0];
            const float inv1 = s_inv[r0 + 8];
            const int col = h * 64 + wg * 8 + (lane & 3) * 2;
            float2 c01 = __half22float2(*(__half2*)&pc[0]);
            float2 c23 = __half22float2(*(__half2*)&pc[1]);
            float v0 = (cacc[0] + c01.x) * inv0;
            float v1 = (cacc[1] + c01.y) * inv0;
            float v2 = (cacc[2] + c23.x) * inv1;
            float v3 = (cacc[3] + c23.y) * inv1;
            __half h0 = __float2half_rn(v0);
            __half h1 = __float2half_rn(v1);
            __half h2 = __float2half_rn(v2);
            __half h3 = __float2half_rn(v3);
            __half2 hp0 = __halves2half2(h0, h1);
            __half2 hp1 = __halves2half2(h2, h3);
            __half2 lp0 = __halves2half2(
                __float2half_rn(v0 - __half2float(h0)),
                __float2half_rn(v1 - __half2float(h1)));
            __half2 lp1 = __halves2half2(
                __float2half_rn(v2 - __half2float(h2)),
                __float2half_rn(v3 - __half2float(h3)));
            *(__half2*)&CtxH[(tokbase + q0 + r0) * 1024 + col]     = hp0;
            *(__half2*)&CtxH[(tokbase + q0 + r0 + 8) * 1024 + col] = hp1;
            *(__half2*)&CtxL[(tokbase + q0 + r0) * 1024 + col]     = lp0;
            *(__half2*)&CtxL[(tokbase + q0 + r0 + 8) * 1024 + col] = lp1;
        }
        __syncthreads();
    }

    float* aout = amean + (tokbase + q0) * LL;
    #pragma unroll 8
    for (int i = 0; i < 64; i++)
        aout[i * 512 + tid] = mean_acc[i] * (1.f / 16.f);
}

// ---------------------------------------------------------------------------
extern "C" void kernel_launch(void* const* d_in, const int* in_sizes, int n_in,
                              void* d_out, int out_size)
{
    const float* q    = (const float*)d_in[0];
    const float* k    = (const float*)d_in[1];
    const float* v    = (const float*)d_in[2];
    const float* mask = (const float*)d_in[3];
    const float* wq   = (const float*)d_in[4];
    const float* bq   = (const float*)d_in[5];
    const float* wk   = (const float*)d_in[6];
    const float* bk   = (const float*)d_in[7];
    const float* wv   = (const float*)d_in[8];
    const float* bv   = (const float*)d_in[9];
    const float* wo   = (const float*)d_in[10];
    const float* bo   = (const float*)d_in[11];

    float* out   = (float*)d_out;
    float* amean = out + (size_t)NTOK * DD;

    __half *ah, *al, *wh, *wl, *qh, *ql, *kh, *kl, *vh, *vl;
    cudaGetSymbolAddress((void**)&ah,  g_ah);
    cudaGetSymbolAddress((void**)&al,  g_al);
    cudaGetSymbolAddress((void**)&wh,  g_wh);
    cudaGetSymbolAddress((void**)&wl,  g_wl);
    cudaGetSymbolAddress((void**)&qh,  g_qh);
    cudaGetSymbolAddress((void**)&ql,  g_ql);
    cudaGetSymbolAddress((void**)&kh,  g_kh);
    cudaGetSymbolAddress((void**)&kl,  g_kl);
    cudaGetSymbolAddress((void**)&vh,  g_vh);
    cudaGetSymbolAddress((void**)&vl,  g_vl);

    static int attr_set = 0;
    if (!attr_set) {
        cudaFuncSetAttribute(gemm_mma,
                             cudaFuncAttributeMaxDynamicSharedMemorySize,
                             GEMM_SMEM_BYTES);
        cudaFuncSetAttribute(attn_tc,
                             cudaFuncAttributeMaxDynamicSharedMemorySize,
                             AT_SMEM);
        attr_set = 1;
    }

    const dim3 gemm_grid(8, 128);
    const dim3 wt_grid(32, 32);
    const int  conv_blocks = (NTOK * DD) / (256 * 4);

    // Q projection (pre-scaled 1/8)
    conv_wt<<<wt_grid, 256>>>(wq, wh, wl);
    conv_split<<<conv_blocks, 256>>>(q, ah, al);
    gemm_mma<<<gemm_grid, 256, GEMM_SMEM_BYTES>>>(ah, al, wh, wl, bq,
                                                  nullptr, qh, ql, 1, 0.125f);
    // K projection
    conv_wt<<<wt_grid, 256>>>(wk, wh, wl);
    conv_split<<<conv_blocks, 256>>>(k, ah, al);
    gemm_mma<<<gemm_grid, 256, GEMM_SMEM_BYTES>>>(ah, al, wh, wl, bk,
                                                  nullptr, kh, kl, 1, 1.0f);
    // V projection
    conv_wt<<<wt_grid, 256>>>(wv, wh, wl);
    conv_split<<<conv_blocks, 256>>>(v, ah, al);
    gemm_mma<<<gemm_grid, 256, GEMM_SMEM_BYTES>>>(ah, al, wh, wl, bv,
                                                  nullptr, vh, vl, 1, 1.0f);

    // Attention -> ctx hi/lo directly into (ah, al)
    dim3 attn_grid(LL / 32, BS);
    attn_tc<<<attn_grid, 512, AT_SMEM>>>(qh, ql, kh, kl, vh, vl,
                                         mask, ah, al, amean);

    // Output projection (fp32 out)
    conv_wt<<<wt_grid, 256>>>(wo, wh, wl);
    gemm_mma<<<gemm_grid, 256, GEMM_SMEM_BYTES>>>(ah, al, wh, wl, bo,
                                                  out, nullptr, nullptr,
                                                  0, 1.0f);
}